// round 6
// baseline (speedup 1.0000x reference)
#include <cuda_runtime.h>
#include <cuda_bf16.h>
#include <cstdint>

#define H_DIM 1024
#define NSEG  8192
#define NIDX  65536
#define MT    128
#define NT    128
#define KC    32                 // K elems per chunk
#define NCH   (H_DIM / KC)       // 32 chunks
#define NB_TILES (H_DIM / NT)    // 8
#define NSTAGE 3
#define SROW  80                 // smem row stride bytes (64B data + 16B pad)
#define TILE_BYTES  (128 * SROW)        // 10240
#define STAGE_BYTES (4 * TILE_BYTES)    // 40960
#define SMEM_TOTAL  (NSTAGE * STAGE_BYTES)   // 122880

// ---------------- device scratch (no allocs allowed) ----------------
__device__ __nv_bfloat16 g_Ahi[NSEG * H_DIM];   // 16 MB
__device__ __nv_bfloat16 g_Alo[NSEG * H_DIM];   // 16 MB
__device__ __nv_bfloat16 g_Bhi[H_DIM * H_DIM];  // 2 MB
__device__ __nv_bfloat16 g_Blo[H_DIM * H_DIM];  // 2 MB
__device__ float         g_part[NB_TILES * NSEG];
__device__ int           g_segstart[NSEG + 1];

// ---------------- helpers ----------------
__device__ __forceinline__ uint32_t smem_u32(const void* p) {
    uint32_t a;
    asm("{ .reg .u64 t; cvta.to.shared.u64 t, %1; cvt.u32.u64 %0, t; }" : "=r"(a) : "l"(p));
    return a;
}

__device__ __forceinline__ float gelu_f(float x) {
    return 0.5f * x * (1.0f + erff(x * 0.70710678118654752f));
}

#define LDM4(R, addr) \
    asm volatile("ldmatrix.sync.aligned.m8n8.x4.shared.b16 {%0,%1,%2,%3}, [%4];" \
                 : "=r"((R)[0]), "=r"((R)[1]), "=r"((R)[2]), "=r"((R)[3]) : "r"(addr))

#define MMA_BF16(C, A, b0, b1) \
    asm volatile("mma.sync.aligned.m16n8k16.row.col.f32.bf16.bf16.f32 " \
                 "{%0,%1,%2,%3}, {%4,%5,%6,%7}, {%8,%9}, {%0,%1,%2,%3};" \
                 : "+f"((C)[0]), "+f"((C)[1]), "+f"((C)[2]), "+f"((C)[3]) \
                 : "r"((A)[0]), "r"((A)[1]), "r"((A)[2]), "r"((A)[3]), "r"(b0), "r"(b1))

#define CP_ASYNC16(dst, src) \
    asm volatile("cp.async.cg.shared.global [%0], [%1], 16;" :: "r"(dst), "l"(src) : "memory")
#define CP_COMMIT() asm volatile("cp.async.commit_group;" ::: "memory")
#define CP_WAIT1()  asm volatile("cp.async.wait_group 1;" ::: "memory")
#define CP_WAIT0()  asm volatile("cp.async.wait_group 0;" ::: "memory")

// ---------------- kernel 0: per-segment bounds (one binary search per segment) ----------------
__global__ void seg_bounds_kernel(const int* __restrict__ seg) {
    int g = blockIdx.x * blockDim.x + threadIdx.x;
    if (g > NSEG) return;
    int lo = 0, hi = NIDX;
    while (lo < hi) { int mid = (lo + hi) >> 1; if (seg[mid] < g) lo = mid + 1; else hi = mid; }
    g_segstart[g] = lo;
}

// ---------------- kernel 1: segment mean -> bf16 hi/lo split ----------------
__global__ void seg_mean_kernel(const float* __restrict__ hid,
                                const int* __restrict__ indices) {
    int g = blockIdx.x;
    int start = g_segstart[g];
    int end   = g_segstart[g + 1];

    int t = threadIdx.x;  // 256 threads, 4 contiguous cols each
    float4 acc = make_float4(0.f, 0.f, 0.f, 0.f);

    int i = start;
    for (; i + 4 <= end; i += 4) {
        int r0 = __ldg(indices + i);
        int r1 = __ldg(indices + i + 1);
        int r2 = __ldg(indices + i + 2);
        int r3 = __ldg(indices + i + 3);
        float4 v0 = __ldg((const float4*)(hid + (size_t)r0 * H_DIM) + t);
        float4 v1 = __ldg((const float4*)(hid + (size_t)r1 * H_DIM) + t);
        float4 v2 = __ldg((const float4*)(hid + (size_t)r2 * H_DIM) + t);
        float4 v3 = __ldg((const float4*)(hid + (size_t)r3 * H_DIM) + t);
        acc.x += v0.x; acc.y += v0.y; acc.z += v0.z; acc.w += v0.w;
        acc.x += v1.x; acc.y += v1.y; acc.z += v1.z; acc.w += v1.w;
        acc.x += v2.x; acc.y += v2.y; acc.z += v2.z; acc.w += v2.w;
        acc.x += v3.x; acc.y += v3.y; acc.z += v3.z; acc.w += v3.w;
    }
    for (; i < end; ++i) {
        int r = __ldg(indices + i);
        float4 v = __ldg((const float4*)(hid + (size_t)r * H_DIM) + t);
        acc.x += v.x; acc.y += v.y; acc.z += v.z; acc.w += v.w;
    }

    int cnt = end - start;
    float inv = 1.0f / (float)(cnt > 0 ? cnt : 1);
    float vals[4] = {acc.x * inv, acc.y * inv, acc.z * inv, acc.w * inv};

    size_t base = (size_t)g * H_DIM + t * 4;
#pragma unroll
    for (int j = 0; j < 4; ++j) {
        float v = vals[j];
        __nv_bfloat16 h16 = __float2bfloat16(v);
        float res = v - __bfloat162float(h16);
        g_Ahi[base + j] = h16;
        g_Alo[base + j] = __float2bfloat16(res);
    }
}

// ---------------- kernel 2: W_dense hi/lo split ----------------
__global__ void wsplit_kernel(const float* __restrict__ W) {
    int i = blockIdx.x * blockDim.x + threadIdx.x;
    float v = W[i];
    __nv_bfloat16 h16 = __float2bfloat16(v);
    float res = v - __bfloat162float(h16);
    g_Bhi[i] = h16;
    g_Blo[i] = __float2bfloat16(res);
}

// ---------------- kernel 3: split-bf16 mma.sync GEMM + GELU + proj epilogue ----------------
// 512 threads, 16 warps in 4x4 grid, warp tile 32(m) x 32(n); 3-stage cp.async pipeline.
__device__ __forceinline__ void load_chunk(uint32_t sb, int stage, int kt,
                                           int m0, int n0, int tid) {
#pragma unroll
    for (int j = 0; j < 4; ++j) {
        int tile = j;                       // 0:Ahi 1:Alo 2:Bhi 3:Blo
        int r = tid >> 2, c = tid & 3;      // 128 rows x 4 x 16B
        const __nv_bfloat16* gp;
        if      (tile == 0) gp = g_Ahi + (size_t)(m0 + r) * H_DIM;
        else if (tile == 1) gp = g_Alo + (size_t)(m0 + r) * H_DIM;
        else if (tile == 2) gp = g_Bhi + (size_t)(n0 + r) * H_DIM;
        else                gp = g_Blo + (size_t)(n0 + r) * H_DIM;
        uint32_t dst = sb + stage * STAGE_BYTES + tile * TILE_BYTES + r * SROW + c * 16;
        size_t gsrc = __cvta_generic_to_global((const void*)(gp + kt * KC + c * 8));
        CP_ASYNC16(dst, gsrc);
    }
    CP_COMMIT();
}

__global__ void __launch_bounds__(512, 1)
gemm_kernel(const float* __restrict__ b_dense, const float* __restrict__ W_proj) {
    extern __shared__ char smem_raw[];
    uint32_t sb = smem_u32(smem_raw);
    int tid = threadIdx.x;
    int lane = tid & 31, wid = tid >> 5;
    int wm = wid >> 2, wn = wid & 3;       // 4 x 4 warp grid; warp tile 32(m) x 32(n)
    int nb = blockIdx.x, mb = blockIdx.y;
    int m0 = mb * MT, n0 = nb * NT;

    float acc[2][4][4];
#pragma unroll
    for (int i = 0; i < 2; ++i)
#pragma unroll
        for (int j = 0; j < 4; ++j)
#pragma unroll
            for (int k = 0; k < 4; ++k) acc[i][j][k] = 0.f;

    // per-thread ldmatrix row/col components (x4 address pattern)
    uint32_t a_row = (((lane >> 3) & 1) << 3) + (lane & 7);
    uint32_t a_kb  = ((lane >> 4) & 1) * 16;
    uint32_t b_row = (((lane >> 4) & 1) << 3) + (lane & 7);
    uint32_t b_kb  = ((lane >> 3) & 1) * 16;

    load_chunk(sb, 0, 0, m0, n0, tid);
    load_chunk(sb, 1, 1, m0, n0, tid);

    for (int kt = 0; kt < NCH; ++kt) {
        if (kt == NCH - 1) { CP_WAIT0(); } else { CP_WAIT1(); }
        __syncthreads();
        // stage (kt+2)%3 == stage (kt-1)%3, fully consumed before the barrier above
        if (kt + 2 < NCH) load_chunk(sb, (kt + 2) % NSTAGE, kt + 2, m0, n0, tid);

        uint32_t s0   = sb + (kt % NSTAGE) * STAGE_BYTES;
        uint32_t a_hi = s0 + (wm * 32) * SROW;
        uint32_t b_hi = s0 + 2 * TILE_BYTES + (wn * 32) * SROW;

#pragma unroll
        for (int k16 = 0; k16 < 2; ++k16) {
            uint32_t kb = k16 * 32;  // 16 bf16 = 32 bytes

            uint32_t Bh[2][4], Bl[2][4];
#pragma unroll
            for (int p = 0; p < 2; ++p) {
                uint32_t addr = b_hi + (p * 16 + b_row) * SROW + kb + b_kb;
                LDM4(Bh[p], addr);
                LDM4(Bl[p], addr + TILE_BYTES);
            }
#pragma unroll
            for (int mi = 0; mi < 2; ++mi) {
                uint32_t Ah[4], Al[4];
                uint32_t addr = a_hi + (mi * 16 + a_row) * SROW + kb + a_kb;
                LDM4(Ah, addr);
                LDM4(Al, addr + TILE_BYTES);
#pragma unroll
                for (int nj = 0; nj < 4; ++nj) {
                    uint32_t bh0 = Bh[nj >> 1][(nj & 1) * 2], bh1 = Bh[nj >> 1][(nj & 1) * 2 + 1];
                    uint32_t bl0 = Bl[nj >> 1][(nj & 1) * 2], bl1 = Bl[nj >> 1][(nj & 1) * 2 + 1];
                    MMA_BF16(acc[mi][nj], Ah, bh0, bh1);  // hi*hi
                    MMA_BF16(acc[mi][nj], Ah, bl0, bl1);  // hi*lo
                    MMA_BF16(acc[mi][nj], Al, bh0, bh1);  // lo*hi
                }
            }
        }
    }

    // ---- epilogue: bias + exact-erf GELU + dot with W_proj over this CTA's 128 n-cols ----
    int q  = lane >> 2;          // row within 8-group
    int cq = (lane & 3) * 2;     // col pair within n8 tile
    float pr[2][2];
    pr[0][0] = pr[0][1] = pr[1][0] = pr[1][1] = 0.f;

    float bv0[4], bv1[4], wv0[4], wv1[4];
#pragma unroll
    for (int nj = 0; nj < 4; ++nj) {
        int n = n0 + wn * 32 + nj * 8 + cq;
        bv0[nj] = __ldg(b_dense + n);     bv1[nj] = __ldg(b_dense + n + 1);
        wv0[nj] = __ldg(W_proj + n);      wv1[nj] = __ldg(W_proj + n + 1);
    }
#pragma unroll
    for (int mi = 0; mi < 2; ++mi)
#pragma unroll
        for (int nj = 0; nj < 4; ++nj) {
            pr[mi][0] += gelu_f(acc[mi][nj][0] + bv0[nj]) * wv0[nj]
                       + gelu_f(acc[mi][nj][1] + bv1[nj]) * wv1[nj];
            pr[mi][1] += gelu_f(acc[mi][nj][2] + bv0[nj]) * wv0[nj]
                       + gelu_f(acc[mi][nj][3] + bv1[nj]) * wv1[nj];
        }
#pragma unroll
    for (int mi = 0; mi < 2; ++mi) {
#pragma unroll
        for (int s = 1; s <= 2; s <<= 1) {
            pr[mi][0] += __shfl_xor_sync(0xffffffffu, pr[mi][0], s);
            pr[mi][1] += __shfl_xor_sync(0xffffffffu, pr[mi][1], s);
        }
    }

    float* red = (float*)smem_raw;       // 4 (warp_n) x 128 rows, overlays tile smem
    __syncthreads();
    if ((lane & 3) == 0) {
#pragma unroll
        for (int mi = 0; mi < 2; ++mi) {
            int rbase = wm * 32 + mi * 16 + q;
            red[wn * 128 + rbase]     = pr[mi][0];
            red[wn * 128 + rbase + 8] = pr[mi][1];
        }
    }
    __syncthreads();
    if (tid < 128) {
        float s = red[tid] + red[128 + tid] + red[256 + tid] + red[384 + tid];
        g_part[(size_t)nb * NSEG + m0 + tid] = s;
    }
}

// ---------------- kernel 4: deterministic partial reduce + b_proj ----------------
__global__ void final_kernel(const float* __restrict__ b_proj, float* __restrict__ out) {
    int g = blockIdx.x * blockDim.x + threadIdx.x;
    float s = b_proj[0];
#pragma unroll
    for (int nbi = 0; nbi < NB_TILES; ++nbi) s += g_part[(size_t)nbi * NSEG + g];
    out[g] = s;
}

// ---------------- launcher ----------------
extern "C" void kernel_launch(void* const* d_in, const int* in_sizes, int n_in,
                              void* d_out, int out_size) {
    const float* hid     = (const float*)d_in[0];
    const int*   indices = (const int*)d_in[1];
    const int*   seg     = (const int*)d_in[2];
    const float* W_dense = (const float*)d_in[3];
    const float* b_dense = (const float*)d_in[4];
    const float* W_proj  = (const float*)d_in[5];
    const float* b_proj  = (const float*)d_in[6];
    float* out = (float*)d_out;

    cudaFuncSetAttribute(gemm_kernel, cudaFuncAttributeMaxDynamicSharedMemorySize, SMEM_TOTAL);

    seg_bounds_kernel<<<(NSEG + 1 + 255) / 256, 256>>>(seg);
    seg_mean_kernel<<<NSEG, 256>>>(hid, indices);
    wsplit_kernel<<<(H_DIM * H_DIM) / 256, 256>>>(W_dense);
    gemm_kernel<<<dim3(NB_TILES, NSEG / MT), 512, SMEM_TOTAL>>>(b_dense, W_proj);
    final_kernel<<<NSEG / 256, 256>>>(b_proj, out);
}

// round 7
// speedup vs baseline: 1.2049x; 1.2049x over previous
#include <cuda_runtime.h>
#include <cuda_bf16.h>
#include <cstdint>

#define H_DIM 1024
#define NSEG  8192
#define NIDX  65536
#define MT    128
#define NT    128
#define KC    64                 // K elems per chunk (128 bytes = swizzle atom row)
#define NCH   (H_DIM / KC)       // 16 chunks
#define NB_TILES (H_DIM / NT)    // 8
#define NSTAGE 3
#define SROW  128                // swizzled rows, no padding
#define TILE_BYTES  (128 * SROW)        // 16384
#define STAGE_BYTES (4 * TILE_BYTES)    // 65536
#define SMEM_TOTAL  (NSTAGE * STAGE_BYTES)   // 196608

// ---------------- device scratch (no allocs allowed) ----------------
__device__ __nv_bfloat16 g_Ahi[NSEG * H_DIM];   // 16 MB
__device__ __nv_bfloat16 g_Alo[NSEG * H_DIM];   // 16 MB
__device__ __nv_bfloat16 g_Bhi[H_DIM * H_DIM];  // 2 MB
__device__ __nv_bfloat16 g_Blo[H_DIM * H_DIM];  // 2 MB
__device__ float         g_part[NB_TILES * NSEG];
__device__ int           g_segstart[NSEG + 1];

// ---------------- helpers ----------------
__device__ __forceinline__ uint32_t smem_u32(const void* p) {
    uint32_t a;
    asm("{ .reg .u64 t; cvta.to.shared.u64 t, %1; cvt.u32.u64 %0, t; }" : "=r"(a) : "l"(p));
    return a;
}

__device__ __forceinline__ float gelu_f(float x) {
    return 0.5f * x * (1.0f + erff(x * 0.70710678118654752f));
}

#define LDM4(R, addr) \
    asm volatile("ldmatrix.sync.aligned.m8n8.x4.shared.b16 {%0,%1,%2,%3}, [%4];" \
                 : "=r"((R)[0]), "=r"((R)[1]), "=r"((R)[2]), "=r"((R)[3]) : "r"(addr))

#define MMA_BF16(C, A, b0, b1) \
    asm volatile("mma.sync.aligned.m16n8k16.row.col.f32.bf16.bf16.f32 " \
                 "{%0,%1,%2,%3}, {%4,%5,%6,%7}, {%8,%9}, {%0,%1,%2,%3};" \
                 : "+f"((C)[0]), "+f"((C)[1]), "+f"((C)[2]), "+f"((C)[3]) \
                 : "r"((A)[0]), "r"((A)[1]), "r"((A)[2]), "r"((A)[3]), "r"(b0), "r"(b1))

#define CP_ASYNC16(dst, src) \
    asm volatile("cp.async.cg.shared.global [%0], [%1], 16;" :: "r"(dst), "l"(src) : "memory")
#define CP_COMMIT() asm volatile("cp.async.commit_group;" ::: "memory")
#define CP_WAIT1()  asm volatile("cp.async.wait_group 1;" ::: "memory")
#define CP_WAIT0()  asm volatile("cp.async.wait_group 0;" ::: "memory")

// ---------------- kernel 0: per-segment bounds ----------------
__global__ void seg_bounds_kernel(const int* __restrict__ seg) {
    int g = blockIdx.x * blockDim.x + threadIdx.x;
    if (g > NSEG) return;
    int lo = 0, hi = NIDX;
    while (lo < hi) { int mid = (lo + hi) >> 1; if (seg[mid] < g) lo = mid + 1; else hi = mid; }
    g_segstart[g] = lo;
}

// ---------------- kernel 1: segment mean -> bf16 hi/lo split ----------------
__global__ void seg_mean_kernel(const float* __restrict__ hid,
                                const int* __restrict__ indices) {
    int g = blockIdx.x;
    int start = g_segstart[g];
    int end   = g_segstart[g + 1];

    int t = threadIdx.x;  // 256 threads, 4 contiguous cols each
    float4 acc = make_float4(0.f, 0.f, 0.f, 0.f);

    int i = start;
    for (; i + 4 <= end; i += 4) {
        int r0 = __ldg(indices + i);
        int r1 = __ldg(indices + i + 1);
        int r2 = __ldg(indices + i + 2);
        int r3 = __ldg(indices + i + 3);
        float4 v0 = __ldg((const float4*)(hid + (size_t)r0 * H_DIM) + t);
        float4 v1 = __ldg((const float4*)(hid + (size_t)r1 * H_DIM) + t);
        float4 v2 = __ldg((const float4*)(hid + (size_t)r2 * H_DIM) + t);
        float4 v3 = __ldg((const float4*)(hid + (size_t)r3 * H_DIM) + t);
        acc.x += v0.x; acc.y += v0.y; acc.z += v0.z; acc.w += v0.w;
        acc.x += v1.x; acc.y += v1.y; acc.z += v1.z; acc.w += v1.w;
        acc.x += v2.x; acc.y += v2.y; acc.z += v2.z; acc.w += v2.w;
        acc.x += v3.x; acc.y += v3.y; acc.z += v3.z; acc.w += v3.w;
    }
    for (; i < end; ++i) {
        int r = __ldg(indices + i);
        float4 v = __ldg((const float4*)(hid + (size_t)r * H_DIM) + t);
        acc.x += v.x; acc.y += v.y; acc.z += v.z; acc.w += v.w;
    }

    int cnt = end - start;
    float inv = 1.0f / (float)(cnt > 0 ? cnt : 1);
    float vals[4] = {acc.x * inv, acc.y * inv, acc.z * inv, acc.w * inv};

    size_t base = (size_t)g * H_DIM + t * 4;
#pragma unroll
    for (int j = 0; j < 4; ++j) {
        float v = vals[j];
        __nv_bfloat16 h16 = __float2bfloat16(v);
        float res = v - __bfloat162float(h16);
        g_Ahi[base + j] = h16;
        g_Alo[base + j] = __float2bfloat16(res);
    }
}

// ---------------- kernel 2: W_dense hi/lo split ----------------
__global__ void wsplit_kernel(const float* __restrict__ W) {
    int i = blockIdx.x * blockDim.x + threadIdx.x;
    float v = W[i];
    __nv_bfloat16 h16 = __float2bfloat16(v);
    float res = v - __bfloat162float(h16);
    g_Bhi[i] = h16;
    g_Blo[i] = __float2bfloat16(res);
}

// ---------------- kernel 3: split-bf16 mma.sync GEMM + GELU + proj epilogue ----------------
// 512 threads, 16 warps 4x4, warp tile 32x32; KC=64 swizzled chunks, 3-stage cp.async.
__device__ __forceinline__ void load_chunk(uint32_t sb, int stage, int kt,
                                           int m0, int n0, int tid) {
    // per tile: 128 rows x 8 x 16B = 1024 lines; 512 threads -> 2 per tile
#pragma unroll
    for (int j = 0; j < 8; ++j) {
        int tile = j >> 1;
        int idx  = ((j & 1) << 9) + tid;   // 0..1023
        int r = idx >> 3, c = idx & 7;
        const __nv_bfloat16* gp;
        if      (tile == 0) gp = g_Ahi + (size_t)(m0 + r) * H_DIM;
        else if (tile == 1) gp = g_Alo + (size_t)(m0 + r) * H_DIM;
        else if (tile == 2) gp = g_Bhi + (size_t)(n0 + r) * H_DIM;
        else                gp = g_Blo + (size_t)(n0 + r) * H_DIM;
        uint32_t bo = (uint32_t)(r << 7) + (uint32_t)(c << 4);
        uint32_t sw = bo ^ ((bo >> 3) & 0x70);
        uint32_t dst = sb + stage * STAGE_BYTES + tile * TILE_BYTES + sw;
        size_t gsrc = __cvta_generic_to_global((const void*)(gp + kt * KC + c * 8));
        CP_ASYNC16(dst, gsrc);
    }
    CP_COMMIT();
}

__global__ void __launch_bounds__(512, 1)
gemm_kernel(const float* __restrict__ b_dense, const float* __restrict__ W_proj) {
    extern __shared__ char smem_raw[];
    uint32_t sb = smem_u32(smem_raw);
    int tid = threadIdx.x;
    int lane = tid & 31, wid = tid >> 5;
    int wm = wid >> 2, wn = wid & 3;       // 4 x 4 warp grid; warp tile 32(m) x 32(n)
    int nb = blockIdx.x, mb = blockIdx.y;
    int m0 = mb * MT, n0 = nb * NT;

    float acc[2][4][4];
#pragma unroll
    for (int i = 0; i < 2; ++i)
#pragma unroll
        for (int j = 0; j < 4; ++j)
#pragma unroll
            for (int k = 0; k < 4; ++k) acc[i][j][k] = 0.f;

    // ldmatrix x4 lane address pattern (row within 16-row pair + 16B col select)
    uint32_t a_row = (((lane >> 3) & 1) << 3) + (lane & 7);
    uint32_t a_kb  = ((lane >> 4) & 1) * 16;
    uint32_t b_row = (((lane >> 4) & 1) << 3) + (lane & 7);
    uint32_t b_kb  = ((lane >> 3) & 1) * 16;
    // swizzle masks depend only on (row & 7)
    uint32_t a_xm = (a_row & 7) << 4;
    uint32_t b_xm = (b_row & 7) << 4;

    load_chunk(sb, 0, 0, m0, n0, tid);
    load_chunk(sb, 1, 1, m0, n0, tid);

    int st_c = 0, st_l = 2;
    for (int kt = 0; kt < NCH; ++kt) {
        if (kt == NCH - 1) { CP_WAIT0(); } else { CP_WAIT1(); }
        __syncthreads();
        if (kt + 2 < NCH) {
            load_chunk(sb, st_l, kt + 2, m0, n0, tid);
            st_l = (st_l == NSTAGE - 1) ? 0 : st_l + 1;
        }

        uint32_t s0 = sb + st_c * STAGE_BYTES;
        st_c = (st_c == NSTAGE - 1) ? 0 : st_c + 1;
        // base addresses: tile + row*128 (swizzle applied to low bits only)
        uint32_t a_base = s0 + ((wm * 32 + a_row) << 7);
        uint32_t b_base = s0 + 2 * TILE_BYTES + ((wn * 32 + b_row) << 7);

#pragma unroll
        for (int k16 = 0; k16 < 4; ++k16) {
            uint32_t kb_a = ((k16 * 32 + a_kb) ^ a_xm);
            uint32_t kb_b = ((k16 * 32 + b_kb) ^ b_xm);

            uint32_t Bh[2][4], Bl[2][4];
#pragma unroll
            for (int p = 0; p < 2; ++p) {
                uint32_t addr = b_base + (p << 11) + kb_b;   // p*16 rows = 16*128B
                LDM4(Bh[p], addr);
                LDM4(Bl[p], addr + TILE_BYTES);
            }
#pragma unroll
            for (int mi = 0; mi < 2; ++mi) {
                uint32_t Ah[4], Al[4];
                uint32_t addr = a_base + (mi << 11) + kb_a;
                LDM4(Ah, addr);
                LDM4(Al, addr + TILE_BYTES);
#pragma unroll
                for (int nj = 0; nj < 4; ++nj) {
                    uint32_t bh0 = Bh[nj >> 1][(nj & 1) * 2], bh1 = Bh[nj >> 1][(nj & 1) * 2 + 1];
                    uint32_t bl0 = Bl[nj >> 1][(nj & 1) * 2], bl1 = Bl[nj >> 1][(nj & 1) * 2 + 1];
                    MMA_BF16(acc[mi][nj], Ah, bh0, bh1);  // hi*hi
                    MMA_BF16(acc[mi][nj], Ah, bl0, bl1);  // hi*lo
                    MMA_BF16(acc[mi][nj], Al, bh0, bh1);  // lo*hi
                }
            }
        }
    }

    // ---- epilogue: bias + exact-erf GELU + dot with W_proj over this CTA's 128 n-cols ----
    int q  = lane >> 2;
    int cq = (lane & 3) * 2;
    float pr[2][2];
    pr[0][0] = pr[0][1] = pr[1][0] = pr[1][1] = 0.f;

    float bv0[4], bv1[4], wv0[4], wv1[4];
#pragma unroll
    for (int nj = 0; nj < 4; ++nj) {
        int n = n0 + wn * 32 + nj * 8 + cq;
        bv0[nj] = __ldg(b_dense + n);     bv1[nj] = __ldg(b_dense + n + 1);
        wv0[nj] = __ldg(W_proj + n);      wv1[nj] = __ldg(W_proj + n + 1);
    }
#pragma unroll
    for (int mi = 0; mi < 2; ++mi)
#pragma unroll
        for (int nj = 0; nj < 4; ++nj) {
            pr[mi][0] += gelu_f(acc[mi][nj][0] + bv0[nj]) * wv0[nj]
                       + gelu_f(acc[mi][nj][1] + bv1[nj]) * wv1[nj];
            pr[mi][1] += gelu_f(acc[mi][nj][2] + bv0[nj]) * wv0[nj]
                       + gelu_f(acc[mi][nj][3] + bv1[nj]) * wv1[nj];
        }
#pragma unroll
    for (int mi = 0; mi < 2; ++mi) {
#pragma unroll
        for (int s = 1; s <= 2; s <<= 1) {
            pr[mi][0] += __shfl_xor_sync(0xffffffffu, pr[mi][0], s);
            pr[mi][1] += __shfl_xor_sync(0xffffffffu, pr[mi][1], s);
        }
    }

    float* red = (float*)smem_raw;       // 4 (warp_n) x 128 rows, overlays tile smem
    __syncthreads();
    if ((lane & 3) == 0) {
#pragma unroll
        for (int mi = 0; mi < 2; ++mi) {
            int rbase = wm * 32 + mi * 16 + q;
            red[wn * 128 + rbase]     = pr[mi][0];
            red[wn * 128 + rbase + 8] = pr[mi][1];
        }
    }
    __syncthreads();
    if (tid < 128) {
        float s = red[tid] + red[128 + tid] + red[256 + tid] + red[384 + tid];
        g_part[(size_t)nb * NSEG + m0 + tid] = s;
    }
}

// ---------------- kernel 4: deterministic partial reduce + b_proj ----------------
__global__ void final_kernel(const float* __restrict__ b_proj, float* __restrict__ out) {
    int g = blockIdx.x * blockDim.x + threadIdx.x;
    float s = b_proj[0];
#pragma unroll
    for (int nbi = 0; nbi < NB_TILES; ++nbi) s += g_part[(size_t)nbi * NSEG + g];
    out[g] = s;
}

// ---------------- launcher ----------------
extern "C" void kernel_launch(void* const* d_in, const int* in_sizes, int n_in,
                              void* d_out, int out_size) {
    const float* hid     = (const float*)d_in[0];
    const int*   indices = (const int*)d_in[1];
    const int*   seg     = (const int*)d_in[2];
    const float* W_dense = (const float*)d_in[3];
    const float* b_dense = (const float*)d_in[4];
    const float* W_proj  = (const float*)d_in[5];
    const float* b_proj  = (const float*)d_in[6];
    float* out = (float*)d_out;

    cudaFuncSetAttribute(gemm_kernel, cudaFuncAttributeMaxDynamicSharedMemorySize, SMEM_TOTAL);

    seg_bounds_kernel<<<(NSEG + 1 + 255) / 256, 256>>>(seg);
    seg_mean_kernel<<<NSEG, 256>>>(hid, indices);
    wsplit_kernel<<<(H_DIM * H_DIM) / 256, 256>>>(W_dense);
    gemm_kernel<<<dim3(NB_TILES, NSEG / MT), 512, SMEM_TOTAL>>>(b_dense, W_proj);
    final_kernel<<<NSEG / 256, 256>>>(b_proj, out);
}

// round 8
// speedup vs baseline: 1.3853x; 1.1498x over previous
#include <cuda_runtime.h>
#include <cuda_bf16.h>
#include <cstdint>

#define H_DIM 1024
#define NSEG  8192
#define NIDX  65536
#define MT    128
#define NT    64                 // CTA N tile (2 CTAs/SM)
#define KC    64                 // K elems per chunk (128 bytes = swizzle atom row)
#define NCH   (H_DIM / KC)       // 16 chunks
#define NB_TILES (H_DIM / NT)    // 16
#define SROW  128                // swizzled rows, no padding
#define A_TILE_BYTES (128 * SROW)       // 16384
#define B_TILE_BYTES (64 * SROW)        // 8192
// stage layout: [Ahi 16K][Alo 16K][Bhi 8K][Blo 8K] = 48K
#define OFF_AHI 0
#define OFF_ALO A_TILE_BYTES
#define OFF_BHI (2 * A_TILE_BYTES)
#define OFF_BLO (2 * A_TILE_BYTES + B_TILE_BYTES)
#define STAGE_BYTES (2 * A_TILE_BYTES + 2 * B_TILE_BYTES)   // 49152
#define SMEM_TOTAL  (2 * STAGE_BYTES)                       // 98304 per CTA

// ---------------- device scratch (no allocs allowed) ----------------
__device__ __nv_bfloat16 g_Ahi[NSEG * H_DIM];   // 16 MB
__device__ __nv_bfloat16 g_Alo[NSEG * H_DIM];   // 16 MB
__device__ __nv_bfloat16 g_Bhi[H_DIM * H_DIM];  // 2 MB
__device__ __nv_bfloat16 g_Blo[H_DIM * H_DIM];  // 2 MB
__device__ float         g_part[NB_TILES * NSEG];
__device__ int           g_segstart[NSEG + 1];

// ---------------- helpers ----------------
__device__ __forceinline__ uint32_t smem_u32(const void* p) {
    uint32_t a;
    asm("{ .reg .u64 t; cvta.to.shared.u64 t, %1; cvt.u32.u64 %0, t; }" : "=r"(a) : "l"(p));
    return a;
}

__device__ __forceinline__ float gelu_f(float x) {
    return 0.5f * x * (1.0f + erff(x * 0.70710678118654752f));
}

#define LDM4(R, addr) \
    asm volatile("ldmatrix.sync.aligned.m8n8.x4.shared.b16 {%0,%1,%2,%3}, [%4];" \
                 : "=r"((R)[0]), "=r"((R)[1]), "=r"((R)[2]), "=r"((R)[3]) : "r"(addr))

#define MMA_BF16(C, A, b0, b1) \
    asm volatile("mma.sync.aligned.m16n8k16.row.col.f32.bf16.bf16.f32 " \
                 "{%0,%1,%2,%3}, {%4,%5,%6,%7}, {%8,%9}, {%0,%1,%2,%3};" \
                 : "+f"((C)[0]), "+f"((C)[1]), "+f"((C)[2]), "+f"((C)[3]) \
                 : "r"((A)[0]), "r"((A)[1]), "r"((A)[2]), "r"((A)[3]), "r"(b0), "r"(b1))

#define CP_ASYNC16(dst, src) \
    asm volatile("cp.async.cg.shared.global [%0], [%1], 16;" :: "r"(dst), "l"(src) : "memory")
#define CP_COMMIT() asm volatile("cp.async.commit_group;" ::: "memory")
#define CP_WAIT1()  asm volatile("cp.async.wait_group 1;" ::: "memory")
#define CP_WAIT0()  asm volatile("cp.async.wait_group 0;" ::: "memory")

// ---------------- kernel 0: per-segment bounds ----------------
__global__ void seg_bounds_kernel(const int* __restrict__ seg) {
    int g = blockIdx.x * blockDim.x + threadIdx.x;
    if (g > NSEG) return;
    int lo = 0, hi = NIDX;
    while (lo < hi) { int mid = (lo + hi) >> 1; if (seg[mid] < g) lo = mid + 1; else hi = mid; }
    g_segstart[g] = lo;
}

// ---------------- kernel 1: segment mean -> bf16 hi/lo split ----------------
__global__ void seg_mean_kernel(const float* __restrict__ hid,
                                const int* __restrict__ indices) {
    int g = blockIdx.x;
    int start = g_segstart[g];
    int end   = g_segstart[g + 1];

    int t = threadIdx.x;  // 256 threads, 4 contiguous cols each
    float4 acc = make_float4(0.f, 0.f, 0.f, 0.f);

    int i = start;
    for (; i + 4 <= end; i += 4) {
        int r0 = __ldg(indices + i);
        int r1 = __ldg(indices + i + 1);
        int r2 = __ldg(indices + i + 2);
        int r3 = __ldg(indices + i + 3);
        float4 v0 = __ldg((const float4*)(hid + (size_t)r0 * H_DIM) + t);
        float4 v1 = __ldg((const float4*)(hid + (size_t)r1 * H_DIM) + t);
        float4 v2 = __ldg((const float4*)(hid + (size_t)r2 * H_DIM) + t);
        float4 v3 = __ldg((const float4*)(hid + (size_t)r3 * H_DIM) + t);
        acc.x += v0.x; acc.y += v0.y; acc.z += v0.z; acc.w += v0.w;
        acc.x += v1.x; acc.y += v1.y; acc.z += v1.z; acc.w += v1.w;
        acc.x += v2.x; acc.y += v2.y; acc.z += v2.z; acc.w += v2.w;
        acc.x += v3.x; acc.y += v3.y; acc.z += v3.z; acc.w += v3.w;
    }
    for (; i < end; ++i) {
        int r = __ldg(indices + i);
        float4 v = __ldg((const float4*)(hid + (size_t)r * H_DIM) + t);
        acc.x += v.x; acc.y += v.y; acc.z += v.z; acc.w += v.w;
    }

    int cnt = end - start;
    float inv = 1.0f / (float)(cnt > 0 ? cnt : 1);
    float vals[4] = {acc.x * inv, acc.y * inv, acc.z * inv, acc.w * inv};

    size_t base = (size_t)g * H_DIM + t * 4;
#pragma unroll
    for (int j = 0; j < 4; ++j) {
        float v = vals[j];
        __nv_bfloat16 h16 = __float2bfloat16(v);
        float res = v - __bfloat162float(h16);
        g_Ahi[base + j] = h16;
        g_Alo[base + j] = __float2bfloat16(res);
    }
}

// ---------------- kernel 2: W_dense hi/lo split ----------------
__global__ void wsplit_kernel(const float* __restrict__ W) {
    int i = blockIdx.x * blockDim.x + threadIdx.x;
    float v = W[i];
    __nv_bfloat16 h16 = __float2bfloat16(v);
    float res = v - __bfloat162float(h16);
    g_Bhi[i] = h16;
    g_Blo[i] = __float2bfloat16(res);
}

// ---------------- kernel 3: split-bf16 mma.sync GEMM + GELU + proj epilogue ----------------
// 256 threads, 8 warps (4x2), warp tile 32x32; CTA tile 128x64; 2 CTAs/SM,
// 2-stage KC=64 swizzled cp.async double buffer.
__device__ __forceinline__ void load_chunk(uint32_t sb, int stage, int kt,
                                           int m0, int n0, int tid) {
    uint32_t sbase = sb + stage * STAGE_BYTES;
    // A tiles: 128 rows x 8 lines = 1024 lines each; 256 threads -> 4 each
#pragma unroll
    for (int j = 0; j < 4; ++j) {
        int idx = (j << 8) + tid;          // 0..1023
        int r = idx >> 3, c = idx & 7;
        uint32_t bo = (uint32_t)(r << 7) + (uint32_t)(c << 4);
        uint32_t sw = bo ^ ((bo >> 3) & 0x70);
        const __nv_bfloat16* ga = g_Ahi + (size_t)(m0 + r) * H_DIM + kt * KC + c * 8;
        const __nv_bfloat16* gl = g_Alo + (size_t)(m0 + r) * H_DIM + kt * KC + c * 8;
        CP_ASYNC16(sbase + OFF_AHI + sw, __cvta_generic_to_global((const void*)ga));
        CP_ASYNC16(sbase + OFF_ALO + sw, __cvta_generic_to_global((const void*)gl));
    }
    // B tiles: 64 rows x 8 lines = 512 lines each; 256 threads -> 2 each
#pragma unroll
    for (int j = 0; j < 2; ++j) {
        int idx = (j << 8) + tid;          // 0..511
        int r = idx >> 3, c = idx & 7;
        uint32_t bo = (uint32_t)(r << 7) + (uint32_t)(c << 4);
        uint32_t sw = bo ^ ((bo >> 3) & 0x70);
        const __nv_bfloat16* gb = g_Bhi + (size_t)(n0 + r) * H_DIM + kt * KC + c * 8;
        const __nv_bfloat16* gl = g_Blo + (size_t)(n0 + r) * H_DIM + kt * KC + c * 8;
        CP_ASYNC16(sbase + OFF_BHI + sw, __cvta_generic_to_global((const void*)gb));
        CP_ASYNC16(sbase + OFF_BLO + sw, __cvta_generic_to_global((const void*)gl));
    }
    CP_COMMIT();
}

__global__ void __launch_bounds__(256, 2)
gemm_kernel(const float* __restrict__ b_dense, const float* __restrict__ W_proj) {
    extern __shared__ char smem_raw[];
    uint32_t sb = smem_u32(smem_raw);
    int tid = threadIdx.x;
    int lane = tid & 31, wid = tid >> 5;
    int wm = wid >> 1, wn = wid & 1;       // 4 x 2 warp grid; warp tile 32(m) x 32(n)
    int nb = blockIdx.x, mb = blockIdx.y;
    int m0 = mb * MT, n0 = nb * NT;

    float acc[2][4][4];
#pragma unroll
    for (int i = 0; i < 2; ++i)
#pragma unroll
        for (int j = 0; j < 4; ++j)
#pragma unroll
            for (int k = 0; k < 4; ++k) acc[i][j][k] = 0.f;

    // ldmatrix x4 lane address pattern
    uint32_t a_row = (((lane >> 3) & 1) << 3) + (lane & 7);
    uint32_t a_kb  = ((lane >> 4) & 1) * 16;
    uint32_t b_row = (((lane >> 4) & 1) << 3) + (lane & 7);
    uint32_t b_kb  = ((lane >> 3) & 1) * 16;
    uint32_t a_xm = (a_row & 7) << 4;
    uint32_t b_xm = (b_row & 7) << 4;

    load_chunk(sb, 0, 0, m0, n0, tid);

    for (int kt = 0; kt < NCH; ++kt) {
        if (kt + 1 < NCH) {
            load_chunk(sb, (kt + 1) & 1, kt + 1, m0, n0, tid);
            CP_WAIT1();            // chunk kt complete (kt+1 still in flight)
        } else {
            CP_WAIT0();
        }
        __syncthreads();

        uint32_t s0 = sb + (kt & 1) * STAGE_BYTES;
        uint32_t a_base = s0 + OFF_AHI + ((wm * 32 + a_row) << 7);
        uint32_t b_base = s0 + OFF_BHI + ((wn * 32 + b_row) << 7);

#pragma unroll
        for (int k16 = 0; k16 < 4; ++k16) {
            uint32_t kb_a = ((k16 * 32 + a_kb) ^ a_xm);
            uint32_t kb_b = ((k16 * 32 + b_kb) ^ b_xm);

            uint32_t Bh[2][4], Bl[2][4];
#pragma unroll
            for (int p = 0; p < 2; ++p) {
                uint32_t addr = b_base + (p << 11) + kb_b;   // p*16 rows = 2048B
                LDM4(Bh[p], addr);
                LDM4(Bl[p], addr + (OFF_BLO - OFF_BHI));
            }
#pragma unroll
            for (int mi = 0; mi < 2; ++mi) {
                uint32_t Ah[4], Al[4];
                uint32_t addr = a_base + (mi << 11) + kb_a;
                LDM4(Ah, addr);
                LDM4(Al, addr + (OFF_ALO - OFF_AHI));
#pragma unroll
                for (int nj = 0; nj < 4; ++nj) {
                    uint32_t bh0 = Bh[nj >> 1][(nj & 1) * 2], bh1 = Bh[nj >> 1][(nj & 1) * 2 + 1];
                    uint32_t bl0 = Bl[nj >> 1][(nj & 1) * 2], bl1 = Bl[nj >> 1][(nj & 1) * 2 + 1];
                    MMA_BF16(acc[mi][nj], Ah, bh0, bh1);  // hi*hi
                    MMA_BF16(acc[mi][nj], Ah, bl0, bl1);  // hi*lo
                    MMA_BF16(acc[mi][nj], Al, bh0, bh1);  // lo*hi
                }
            }
        }
        __syncthreads();   // compute done before next iter overwrites this stage
    }

    // ---- epilogue: bias + exact-erf GELU + dot with W_proj over this CTA's 64 n-cols ----
    int q  = lane >> 2;
    int cq = (lane & 3) * 2;
    float pr[2][2];
    pr[0][0] = pr[0][1] = pr[1][0] = pr[1][1] = 0.f;

    float bv0[4], bv1[4], wv0[4], wv1[4];
#pragma unroll
    for (int nj = 0; nj < 4; ++nj) {
        int n = n0 + wn * 32 + nj * 8 + cq;
        bv0[nj] = __ldg(b_dense + n);     bv1[nj] = __ldg(b_dense + n + 1);
        wv0[nj] = __ldg(W_proj + n);      wv1[nj] = __ldg(W_proj + n + 1);
    }
#pragma unroll
    for (int mi = 0; mi < 2; ++mi)
#pragma unroll
        for (int nj = 0; nj < 4; ++nj) {
            pr[mi][0] += gelu_f(acc[mi][nj][0] + bv0[nj]) * wv0[nj]
                       + gelu_f(acc[mi][nj][1] + bv1[nj]) * wv1[nj];
            pr[mi][1] += gelu_f(acc[mi][nj][2] + bv0[nj]) * wv0[nj]
                       + gelu_f(acc[mi][nj][3] + bv1[nj]) * wv1[nj];
        }
#pragma unroll
    for (int mi = 0; mi < 2; ++mi) {
#pragma unroll
        for (int s = 1; s <= 2; s <<= 1) {
            pr[mi][0] += __shfl_xor_sync(0xffffffffu, pr[mi][0], s);
            pr[mi][1] += __shfl_xor_sync(0xffffffffu, pr[mi][1], s);
        }
    }

    float* red = (float*)smem_raw;       // 2 (warp_n) x 128 rows, overlays tile smem
    __syncthreads();
    if ((lane & 3) == 0) {
#pragma unroll
        for (int mi = 0; mi < 2; ++mi) {
            int rbase = wm * 32 + mi * 16 + q;
            red[wn * 128 + rbase]     = pr[mi][0];
            red[wn * 128 + rbase + 8] = pr[mi][1];
        }
    }
    __syncthreads();
    if (tid < 128) {
        float s = red[tid] + red[128 + tid];
        g_part[(size_t)nb * NSEG + m0 + tid] = s;
    }
}

// ---------------- kernel 4: deterministic partial reduce + b_proj ----------------
__global__ void final_kernel(const float* __restrict__ b_proj, float* __restrict__ out) {
    int g = blockIdx.x * blockDim.x + threadIdx.x;
    float s = b_proj[0];
#pragma unroll
    for (int nbi = 0; nbi < NB_TILES; ++nbi) s += g_part[(size_t)nbi * NSEG + g];
    out[g] = s;
}

// ---------------- launcher ----------------
extern "C" void kernel_launch(void* const* d_in, const int* in_sizes, int n_in,
                              void* d_out, int out_size) {
    const float* hid     = (const float*)d_in[0];
    const int*   indices = (const int*)d_in[1];
    const int*   seg     = (const int*)d_in[2];
    const float* W_dense = (const float*)d_in[3];
    const float* b_dense = (const float*)d_in[4];
    const float* W_proj  = (const float*)d_in[5];
    const float* b_proj  = (const float*)d_in[6];
    float* out = (float*)d_out;

    cudaFuncSetAttribute(gemm_kernel, cudaFuncAttributeMaxDynamicSharedMemorySize, SMEM_TOTAL);

    seg_bounds_kernel<<<(NSEG + 1 + 255) / 256, 256>>>(seg);
    seg_mean_kernel<<<NSEG, 256>>>(hid, indices);
    wsplit_kernel<<<(H_DIM * H_DIM) / 256, 256>>>(W_dense);
    gemm_kernel<<<dim3(NB_TILES, NSEG / MT), 256, SMEM_TOTAL>>>(b_dense, W_proj);
    final_kernel<<<NSEG / 256, 256>>>(b_proj, out);
}

// round 9
// speedup vs baseline: 1.7506x; 1.2637x over previous
#include <cuda_runtime.h>
#include <cuda_fp16.h>
#include <cstdint>

#define H_DIM 1024
#define NSEG  8192
#define NIDX  65536
#define MT    128
#define NT    64                 // CTA N tile (2 CTAs/SM)
#define KC    64                 // K elems per chunk (128 bytes = swizzle atom row)
#define NCH   (H_DIM / KC)       // 16 chunks
#define NB_TILES (H_DIM / NT)    // 16
#define NSTAGE 3
#define SROW  128
#define A_TILE_BYTES (128 * SROW)       // 16384
#define B_TILE_BYTES (64 * SROW)        // 8192
// stage layout: [A 16K][Bhi 8K][Blo 8K] = 32K
#define OFF_A   0
#define OFF_BHI A_TILE_BYTES
#define OFF_BLO (A_TILE_BYTES + B_TILE_BYTES)
#define STAGE_BYTES (A_TILE_BYTES + 2 * B_TILE_BYTES)   // 32768
#define SMEM_TOTAL  (NSTAGE * STAGE_BYTES)              // 98304 per CTA

// ---------------- device scratch (no allocs allowed) ----------------
__device__ __half g_Ah[NSEG * H_DIM];    // 16 MB  (A as fp16)
__device__ __half g_Bhi[H_DIM * H_DIM];  // 2 MB   (W fp16 hi)
__device__ __half g_Blo[H_DIM * H_DIM];  // 2 MB   (W fp16 residual)
__device__ float  g_part[NB_TILES * NSEG];
__device__ int    g_segstart[NSEG + 1];

// ---------------- helpers ----------------
__device__ __forceinline__ uint32_t smem_u32(const void* p) {
    uint32_t a;
    asm("{ .reg .u64 t; cvta.to.shared.u64 t, %1; cvt.u32.u64 %0, t; }" : "=r"(a) : "l"(p));
    return a;
}

__device__ __forceinline__ float gelu_f(float x) {
    return 0.5f * x * (1.0f + erff(x * 0.70710678118654752f));
}

#define LDM4(R, addr) \
    asm volatile("ldmatrix.sync.aligned.m8n8.x4.shared.b16 {%0,%1,%2,%3}, [%4];" \
                 : "=r"((R)[0]), "=r"((R)[1]), "=r"((R)[2]), "=r"((R)[3]) : "r"(addr))

#define MMA_F16(C, A, b0, b1) \
    asm volatile("mma.sync.aligned.m16n8k16.row.col.f32.f16.f16.f32 " \
                 "{%0,%1,%2,%3}, {%4,%5,%6,%7}, {%8,%9}, {%0,%1,%2,%3};" \
                 : "+f"((C)[0]), "+f"((C)[1]), "+f"((C)[2]), "+f"((C)[3]) \
                 : "r"((A)[0]), "r"((A)[1]), "r"((A)[2]), "r"((A)[3]), "r"(b0), "r"(b1))

#define CP_ASYNC16(dst, src) \
    asm volatile("cp.async.cg.shared.global [%0], [%1], 16;" :: "r"(dst), "l"(src) : "memory")
#define CP_COMMIT() asm volatile("cp.async.commit_group;" ::: "memory")
#define CP_WAIT1()  asm volatile("cp.async.wait_group 1;" ::: "memory")
#define CP_WAIT0()  asm volatile("cp.async.wait_group 0;" ::: "memory")

// ---------------- kernel 0: per-segment bounds ----------------
__global__ void seg_bounds_kernel(const int* __restrict__ seg) {
    int g = blockIdx.x * blockDim.x + threadIdx.x;
    if (g > NSEG) return;
    int lo = 0, hi = NIDX;
    while (lo < hi) { int mid = (lo + hi) >> 1; if (seg[mid] < g) lo = mid + 1; else hi = mid; }
    g_segstart[g] = lo;
}

// ---------------- kernel 1: segment mean -> fp16 ----------------
__global__ void seg_mean_kernel(const float* __restrict__ hid,
                                const int* __restrict__ indices) {
    int g = blockIdx.x;
    int start = g_segstart[g];
    int end   = g_segstart[g + 1];

    int t = threadIdx.x;  // 256 threads, 4 contiguous cols each
    float4 acc = make_float4(0.f, 0.f, 0.f, 0.f);

    int i = start;
    for (; i + 4 <= end; i += 4) {
        int r0 = __ldg(indices + i);
        int r1 = __ldg(indices + i + 1);
        int r2 = __ldg(indices + i + 2);
        int r3 = __ldg(indices + i + 3);
        float4 v0 = __ldg((const float4*)(hid + (size_t)r0 * H_DIM) + t);
        float4 v1 = __ldg((const float4*)(hid + (size_t)r1 * H_DIM) + t);
        float4 v2 = __ldg((const float4*)(hid + (size_t)r2 * H_DIM) + t);
        float4 v3 = __ldg((const float4*)(hid + (size_t)r3 * H_DIM) + t);
        acc.x += v0.x; acc.y += v0.y; acc.z += v0.z; acc.w += v0.w;
        acc.x += v1.x; acc.y += v1.y; acc.z += v1.z; acc.w += v1.w;
        acc.x += v2.x; acc.y += v2.y; acc.z += v2.z; acc.w += v2.w;
        acc.x += v3.x; acc.y += v3.y; acc.z += v3.z; acc.w += v3.w;
    }
    for (; i < end; ++i) {
        int r = __ldg(indices + i);
        float4 v = __ldg((const float4*)(hid + (size_t)r * H_DIM) + t);
        acc.x += v.x; acc.y += v.y; acc.z += v.z; acc.w += v.w;
    }

    int cnt = end - start;
    float inv = 1.0f / (float)(cnt > 0 ? cnt : 1);

    __half2 h01 = __floats2half2_rn(acc.x * inv, acc.y * inv);
    __half2 h23 = __floats2half2_rn(acc.z * inv, acc.w * inv);
    *((__half2*)(g_Ah + (size_t)g * H_DIM + t * 4))     = h01;
    *((__half2*)(g_Ah + (size_t)g * H_DIM + t * 4 + 2)) = h23;
}

// ---------------- kernel 2: W_dense fp16 hi/lo split ----------------
__global__ void wsplit_kernel(const float* __restrict__ W) {
    int i = blockIdx.x * blockDim.x + threadIdx.x;
    float v = W[i];
    __half h16 = __float2half_rn(v);
    float res = v - __half2float(h16);
    g_Bhi[i] = h16;
    g_Blo[i] = __float2half_rn(res);
}

// ---------------- kernel 3: fp16 2-pass mma.sync GEMM + GELU + proj epilogue ----------------
// 256 threads, 8 warps (4x2), warp tile 32x32; CTA tile 128x64; 2 CTAs/SM,
// 3-stage KC=64 swizzled cp.async pipeline, single barrier per chunk.
__device__ __forceinline__ void load_chunk(uint32_t sb, int stage, int kt,
                                           int m0, int n0, int tid) {
    uint32_t sbase = sb + stage * STAGE_BYTES;
    // A tile: 128 rows x 8 lines = 1024 lines; 256 threads -> 4 each
#pragma unroll
    for (int j = 0; j < 4; ++j) {
        int idx = (j << 8) + tid;
        int r = idx >> 3, c = idx & 7;
        uint32_t bo = (uint32_t)(r << 7) + (uint32_t)(c << 4);
        uint32_t sw = bo ^ ((bo >> 3) & 0x70);
        const __half* ga = g_Ah + (size_t)(m0 + r) * H_DIM + kt * KC + c * 8;
        CP_ASYNC16(sbase + OFF_A + sw, __cvta_generic_to_global((const void*)ga));
    }
    // B tiles: 64 rows x 8 lines = 512 lines each; 256 threads -> 2 each
#pragma unroll
    for (int j = 0; j < 2; ++j) {
        int idx = (j << 8) + tid;
        int r = idx >> 3, c = idx & 7;
        uint32_t bo = (uint32_t)(r << 7) + (uint32_t)(c << 4);
        uint32_t sw = bo ^ ((bo >> 3) & 0x70);
        const __half* gb = g_Bhi + (size_t)(n0 + r) * H_DIM + kt * KC + c * 8;
        const __half* gl = g_Blo + (size_t)(n0 + r) * H_DIM + kt * KC + c * 8;
        CP_ASYNC16(sbase + OFF_BHI + sw, __cvta_generic_to_global((const void*)gb));
        CP_ASYNC16(sbase + OFF_BLO + sw, __cvta_generic_to_global((const void*)gl));
    }
    CP_COMMIT();
}

__global__ void __launch_bounds__(256, 2)
gemm_kernel(const float* __restrict__ b_dense, const float* __restrict__ W_proj) {
    extern __shared__ char smem_raw[];
    uint32_t sb = smem_u32(smem_raw);
    int tid = threadIdx.x;
    int lane = tid & 31, wid = tid >> 5;
    int wm = wid >> 1, wn = wid & 1;       // 4 x 2 warp grid; warp tile 32(m) x 32(n)
    int nb = blockIdx.x, mb = blockIdx.y;
    int m0 = mb * MT, n0 = nb * NT;

    float acc[2][4][4];
#pragma unroll
    for (int i = 0; i < 2; ++i)
#pragma unroll
        for (int j = 0; j < 4; ++j)
#pragma unroll
            for (int k = 0; k < 4; ++k) acc[i][j][k] = 0.f;

    // ldmatrix x4 lane address pattern
    uint32_t a_row = (((lane >> 3) & 1) << 3) + (lane & 7);
    uint32_t a_kb  = ((lane >> 4) & 1) * 16;
    uint32_t b_row = (((lane >> 4) & 1) << 3) + (lane & 7);
    uint32_t b_kb  = ((lane >> 3) & 1) * 16;
    uint32_t a_xm = (a_row & 7) << 4;
    uint32_t b_xm = (b_row & 7) << 4;

    load_chunk(sb, 0, 0, m0, n0, tid);
    load_chunk(sb, 1, 1, m0, n0, tid);

    for (int kt = 0; kt < NCH; ++kt) {
        if (kt == NCH - 1) { CP_WAIT0(); } else { CP_WAIT1(); }
        __syncthreads();   // all warps past chunk kt-1 compute; chunk kt data visible
        if (kt + 2 < NCH) load_chunk(sb, (kt + 2) % NSTAGE, kt + 2, m0, n0, tid);

        uint32_t s0 = sb + (kt % NSTAGE) * STAGE_BYTES;
        uint32_t a_base = s0 + OFF_A   + ((wm * 32 + a_row) << 7);
        uint32_t b_base = s0 + OFF_BHI + ((wn * 32 + b_row) << 7);

#pragma unroll
        for (int k16 = 0; k16 < 4; ++k16) {
            uint32_t kb_a = ((k16 * 32 + a_kb) ^ a_xm);
            uint32_t kb_b = ((k16 * 32 + b_kb) ^ b_xm);

            uint32_t Bh[2][4], Bl[2][4];
#pragma unroll
            for (int p = 0; p < 2; ++p) {
                uint32_t addr = b_base + (p << 11) + kb_b;   // p*16 rows = 2048B
                LDM4(Bh[p], addr);
                LDM4(Bl[p], addr + (OFF_BLO - OFF_BHI));
            }
#pragma unroll
            for (int mi = 0; mi < 2; ++mi) {
                uint32_t Af[4];
                LDM4(Af, a_base + (mi << 11) + kb_a);
#pragma unroll
                for (int nj = 0; nj < 4; ++nj) {
                    uint32_t bh0 = Bh[nj >> 1][(nj & 1) * 2], bh1 = Bh[nj >> 1][(nj & 1) * 2 + 1];
                    uint32_t bl0 = Bl[nj >> 1][(nj & 1) * 2], bl1 = Bl[nj >> 1][(nj & 1) * 2 + 1];
                    MMA_F16(acc[mi][nj], Af, bh0, bh1);  // A * B_hi
                    MMA_F16(acc[mi][nj], Af, bl0, bl1);  // A * B_lo
                }
            }
        }
    }

    // ---- epilogue: bias + exact-erf GELU + dot with W_proj over this CTA's 64 n-cols ----
    int q  = lane >> 2;
    int cq = (lane & 3) * 2;
    float pr[2][2];
    pr[0][0] = pr[0][1] = pr[1][0] = pr[1][1] = 0.f;

    float bv0[4], bv1[4], wv0[4], wv1[4];
#pragma unroll
    for (int nj = 0; nj < 4; ++nj) {
        int n = n0 + wn * 32 + nj * 8 + cq;
        bv0[nj] = __ldg(b_dense + n);     bv1[nj] = __ldg(b_dense + n + 1);
        wv0[nj] = __ldg(W_proj + n);      wv1[nj] = __ldg(W_proj + n + 1);
    }
#pragma unroll
    for (int mi = 0; mi < 2; ++mi)
#pragma unroll
        for (int nj = 0; nj < 4; ++nj) {
            pr[mi][0] += gelu_f(acc[mi][nj][0] + bv0[nj]) * wv0[nj]
                       + gelu_f(acc[mi][nj][1] + bv1[nj]) * wv1[nj];
            pr[mi][1] += gelu_f(acc[mi][nj][2] + bv0[nj]) * wv0[nj]
                       + gelu_f(acc[mi][nj][3] + bv1[nj]) * wv1[nj];
        }
#pragma unroll
    for (int mi = 0; mi < 2; ++mi) {
#pragma unroll
        for (int s = 1; s <= 2; s <<= 1) {
            pr[mi][0] += __shfl_xor_sync(0xffffffffu, pr[mi][0], s);
            pr[mi][1] += __shfl_xor_sync(0xffffffffu, pr[mi][1], s);
        }
    }

    float* red = (float*)smem_raw;       // 2 (warp_n) x 128 rows, overlays tile smem
    __syncthreads();
    if ((lane & 3) == 0) {
#pragma unroll
        for (int mi = 0; mi < 2; ++mi) {
            int rbase = wm * 32 + mi * 16 + q;
            red[wn * 128 + rbase]     = pr[mi][0];
            red[wn * 128 + rbase + 8] = pr[mi][1];
        }
    }
    __syncthreads();
    if (tid < 128) {
        float s = red[tid] + red[128 + tid];
        g_part[(size_t)nb * NSEG + m0 + tid] = s;
    }
}

// ---------------- kernel 4: deterministic partial reduce + b_proj ----------------
__global__ void final_kernel(const float* __restrict__ b_proj, float* __restrict__ out) {
    int g = blockIdx.x * blockDim.x + threadIdx.x;
    float s = b_proj[0];
#pragma unroll
    for (int nbi = 0; nbi < NB_TILES; ++nbi) s += g_part[(size_t)nbi * NSEG + g];
    out[g] = s;
}

// ---------------- launcher ----------------
extern "C" void kernel_launch(void* const* d_in, const int* in_sizes, int n_in,
                              void* d_out, int out_size) {
    const float* hid     = (const float*)d_in[0];
    const int*   indices = (const int*)d_in[1];
    const int*   seg     = (const int*)d_in[2];
    const float* W_dense = (const float*)d_in[3];
    const float* b_dense = (const float*)d_in[4];
    const float* W_proj  = (const float*)d_in[5];
    const float* b_proj  = (const float*)d_in[6];
    float* out = (float*)d_out;

    cudaFuncSetAttribute(gemm_kernel, cudaFuncAttributeMaxDynamicSharedMemorySize, SMEM_TOTAL);

    seg_bounds_kernel<<<(NSEG + 1 + 255) / 256, 256>>>(seg);
    seg_mean_kernel<<<NSEG, 256>>>(hid, indices);
    wsplit_kernel<<<(H_DIM * H_DIM) / 256, 256>>>(W_dense);
    gemm_kernel<<<dim3(NB_TILES, NSEG / MT), 256, SMEM_TOTAL>>>(b_dense, W_proj);
    final_kernel<<<NSEG / 256, 256>>>(b_proj, out);
}